// round 8
// baseline (speedup 1.0000x reference)
#include <cuda_runtime.h>
#include <cstdint>

#define B_   8
#define CIN  96
#define CMID 48
#define HH   256
#define WW   256
#define H2   128
#define W2   128
#define CO   192

// conv1 output y in fp16: [b][oc][h][w], stored as half2 (adjacent pixels). 50 MB.
__device__ unsigned g_yh[B_ * CMID * HH * WW / 2];
// Pre-packed fp16 weights: [chunk6][tap9][icp8][oc48] half2 (lo = even ic)
__device__ unsigned g_wph[6 * 9 * 8 * 48];
// Pre-packed, pre-padded fp16 x: [b][icp48][row 258][col 264] half2. ~105 MB.
#define XPR 258
#define XPC 264
__device__ unsigned g_xh[B_ * 48 * XPR * XPC];

__device__ __forceinline__ unsigned pack_h2(float lo, float hi) {
    unsigned r;
    asm("{ .reg .b16 l, h; cvt.rn.f16.f32 l, %1; cvt.rn.f16.f32 h, %2; "
        "mov.b32 %0, {l, h}; }" : "=r"(r) : "f"(lo), "f"(hi));
    return r;
}
__device__ __forceinline__ float2 h2f2(unsigned h) {
    float2 f;
    asm("{ .reg .b16 l, h; mov.b32 {l, h}, %2; "
        "cvt.f32.f16 %0, l; cvt.f32.f16 %1, h; }"
        : "=f"(f.x), "=f"(f.y) : "r"(h));
    return f;
}

__device__ __forceinline__ void mma_f16(float* c,
    unsigned a0, unsigned a1, unsigned a2, unsigned a3,
    unsigned b0, unsigned b1)
{
    asm volatile(
        "mma.sync.aligned.m16n8k16.row.col.f32.f16.f16.f32 "
        "{%0,%1,%2,%3}, {%4,%5,%6,%7}, {%8,%9}, {%0,%1,%2,%3};"
        : "+f"(c[0]), "+f"(c[1]), "+f"(c[2]), "+f"(c[3])
        : "r"(a0), "r"(a1), "r"(a2), "r"(a3), "r"(b0), "r"(b1));
}

__device__ __forceinline__ uint32_t smem_u32(const void* p) {
    uint32_t a;
    asm("{ .reg .u64 t; cvta.to.shared.u64 t, %1; cvt.u32.u64 %0, t; }"
        : "=r"(a) : "l"(p));
    return a;
}
#define CP_ASYNC16(dst, src) \
    asm volatile("cp.async.cg.shared.global [%0], [%1], 16;" \
                 :: "r"(dst), "l"(src))
#define CP_COMMIT() asm volatile("cp.async.commit_group;" ::: "memory")
#define CP_WAIT1()  asm volatile("cp.async.wait_group 1;" ::: "memory")
#define CP_WAIT0()  asm volatile("cp.async.wait_group 0;" ::: "memory")

// ---------------------------------------------------------------------------
// Fused prepass: weights (first WN threads) then x relayout.
// ---------------------------------------------------------------------------
#define WN   (6 * 9 * 8 * 48)
#define PX_N (B_ * 48 * XPR * (XPC / 4))

__global__ void prep_kernel(const float* __restrict__ x,
                            const float* __restrict__ w)
{
    int i = blockIdx.x * 256 + threadIdx.x;
    if (i < WN) {
        int chunk = i / 3456;
        int r  = i % 3456;
        int tap = r / 384;
        int r2  = r % 384;
        int icp = r2 / 48;
        int oc  = r2 % 48;
        int ic  = chunk * 16 + icp * 2;
        g_wph[i] = pack_h2(w[(oc * 96 + ic) * 9 + tap],
                           w[(oc * 96 + ic + 1) * 9 + tap]);
        return;
    }
    i -= WN;
    if (i >= PX_N) return;
    int pc0 = (i % (XPC / 4)) * 4;
    int t   = i / (XPC / 4);
    int pr  = t % XPR;
    int t2  = t / XPR;
    int icp = t2 % 48;
    int b   = t2 / 48;
    int gr  = pr - 1;
    const float* s0 = x + ((size_t)((b * CIN + icp * 2) * HH + gr)) * WW;
    const float* s1 = s0 + (size_t)HH * WW;
    bool rok = ((unsigned)gr < (unsigned)HH);
    unsigned res[4];
    #pragma unroll
    for (int j = 0; j < 4; j++) {
        int ww = pc0 + j - 1;
        bool ok = rok && ((unsigned)ww < (unsigned)WW);
        float f0 = ok ? s0[ww] : 0.f;
        float f1 = ok ? s1[ww] : 0.f;
        res[j] = pack_h2(f0, f1);
    }
    *(uint4*)&g_xh[((size_t)(b * 48 + icp) * XPR + pr) * XPC + pc0] =
        *(uint4*)res;
}

// ---------------------------------------------------------------------------
// conv1 via mma.sync fp16 m16n8k16, cp.async double-buffered pipeline.
// (unchanged from round 7)
// ---------------------------------------------------------------------------
#define XS_WORDS (8 * 6 * 132)   // 6336
#define WS_WORDS (9 * 8 * 56)    // 4032
#define SMEM_SZ  ((2 * XS_WORDS + 2 * WS_WORDS) * 4)

__global__ __launch_bounds__(256) void conv1_mma_kernel()
{
    extern __shared__ unsigned sm[];
    unsigned* xs0 = sm;
    unsigned* ws0 = sm + 2 * XS_WORDS;

    const int tid  = threadIdx.x;
    const int lane = tid & 31;
    const int wid  = tid >> 5;
    const int g    = lane >> 2;
    const int u    = lane & 3;

    const int w0 = blockIdx.x * 128;
    const int h0 = blockIdx.y * 4;
    const int b  = blockIdx.z;

    const int wrow  = wid >> 1;
    const int wcolb = (wid & 1) * 64;

    const uint32_t xs_sm = smem_u32(xs0);
    const uint32_t ws_sm = smem_u32(ws0);

    auto issue = [&](int chunk, int buf) {
        const unsigned* srcp =
            g_xh + ((size_t)(b * 48 + chunk * 8 + wid) * XPR + h0) * XPC + w0;
        uint32_t xd = xs_sm + (buf * XS_WORDS + wid * (6 * 132)) * 4;
        for (int j = lane; j < 198; j += 32) {
            int r = j / 33, q = j - r * 33;
            CP_ASYNC16(xd + (r * 132 + q * 4) * 4,
                       srcp + (size_t)r * XPC + q * 4);
        }
        const unsigned* wsrc = g_wph + chunk * 3456;
        uint32_t wd = ws_sm + buf * WS_WORDS * 4;
        for (int j = lane; j < 108; j += 32) {
            int rr = wid * 9 + j / 12, q = j % 12;
            CP_ASYNC16(wd + (rr * 56 + q * 4) * 4, wsrc + rr * 48 + q * 4);
        }
    };

    float acc[4][6][4];
    #pragma unroll
    for (int t = 0; t < 4; t++)
        #pragma unroll
        for (int n = 0; n < 6; n++)
            #pragma unroll
            for (int k = 0; k < 4; k++)
                acc[t][n][k] = 0.f;

    issue(0, 0);
    CP_COMMIT();

    for (int chunk = 0; chunk < 6; chunk++) {
        const int buf = chunk & 1;
        if (chunk < 5) {
            issue(chunk + 1, buf ^ 1);
            CP_COMMIT();
            CP_WAIT1();
        } else {
            CP_WAIT0();
        }
        __syncthreads();

        const unsigned* xsb = xs0 + buf * XS_WORDS;
        const unsigned* wsb = ws0 + buf * WS_WORDS;

        #pragma unroll
        for (int tap = 0; tap < 9; tap++) {
            const int kh = tap / 3, kw = tap % 3;
            const int xr = wrow + kh;

            unsigned bf[6][2];
            #pragma unroll
            for (int n = 0; n < 6; n++) {
                bf[n][0] = wsb[(tap * 8 + u) * 56 + n * 8 + g];
                bf[n][1] = wsb[(tap * 8 + u + 4) * 56 + n * 8 + g];
            }
            #pragma unroll
            for (int t = 0; t < 4; t++) {
                const int colc = wcolb + t * 16 + g + kw;
                unsigned a0 = xsb[(u * 6 + xr) * 132 + colc];
                unsigned a1 = xsb[(u * 6 + xr) * 132 + colc + 8];
                unsigned a2 = xsb[((u + 4) * 6 + xr) * 132 + colc];
                unsigned a3 = xsb[((u + 4) * 6 + xr) * 132 + colc + 8];
                #pragma unroll
                for (int n = 0; n < 6; n++)
                    mma_f16(acc[t][n], a0, a1, a2, a3, bf[n][0], bf[n][1]);
            }
        }
        __syncthreads();
    }

    #pragma unroll
    for (int t = 0; t < 4; t++) {
        const int p0 = wid * 64 + t * 16 + g;
        const int h  = h0 + (p0 >> 7);
        const int hc = ((w0 + (p0 & 127)) >> 1);
        #pragma unroll
        for (int n = 0; n < 6; n++) {
            const int oc = n * 8 + 2 * u;
            float q0 = __shfl_xor_sync(0xffffffffu, acc[t][n][0], 4);
            float q1 = __shfl_xor_sync(0xffffffffu, acc[t][n][1], 4);
            float q2 = __shfl_xor_sync(0xffffffffu, acc[t][n][2], 4);
            float q3 = __shfl_xor_sync(0xffffffffu, acc[t][n][3], 4);
            if (!(g & 1)) {
                unsigned* base =
                    g_yh + ((size_t)(b * CMID + oc) * HH + h) * 128 + hc;
                base[0]                       = pack_h2(acc[t][n][0], q0);
                base[(size_t)HH * WW / 2]     = pack_h2(acc[t][n][1], q1);
                base[4]                       = pack_h2(acc[t][n][2], q2);
                base[(size_t)HH * WW / 2 + 4] = pack_h2(acc[t][n][3], q3);
            }
        }
    }
}

// ---------------------------------------------------------------------------
// Kernel B v3: mask hoisted into registers, loop over 6 y-channels per CTA.
// CTA tile: 16 out rows x 128 cols, thread = 2 rows x 4 cols x (dx0,dx1).
// grid: (H2/16, 2dy x 8 cgroups, B_)
// ---------------------------------------------------------------------------
#define CPG 6   // channels per CTA

__global__ __launch_bounds__(256) void conv2_kernel(
    const float* __restrict__ mask, const float* __restrict__ wp,
    float* __restrict__ out)
{
    __shared__ __align__(16) float smm[2][18][132];
    __shared__ __align__(16) float sy[2][18][132];
    __shared__ float swp[CPG][36];

    const int tid  = threadIdx.x;
    const int hb   = blockIdx.x * 16;
    const int dy   = blockIdx.y & 1;
    const int c0   = (blockIdx.y >> 1) * CPG;
    const int b    = blockIdx.z;

    // ---- stage mask tile (de-interleaved by dx parity) ----
    for (int idx = tid; idx < 18 * 64; idx += 256) {
        int r  = idx >> 6;
        int q2 = (idx & 63) * 2;
        int gy = 2 * (hb - 1 + r) + dy;
        float4 mv = make_float4(0.f, 0.f, 0.f, 0.f);
        if ((unsigned)gy < (unsigned)HH)
            mv = *(const float4*)&mask[((size_t)(b * HH) + gy) * WW + 2 * q2];
        smm[0][r][1 + q2] = mv.x; smm[1][r][1 + q2] = mv.y;
        smm[0][r][2 + q2] = mv.z; smm[1][r][2 + q2] = mv.w;
    }
    if (tid < 18) {
        smm[0][tid][0] = 0.f;   smm[1][tid][0] = 0.f;
        smm[0][tid][129] = 0.f; smm[1][tid][129] = 0.f;
        sy[0][tid][0] = 0.f;    sy[1][tid][0] = 0.f;
        sy[0][tid][129] = 0.f;  sy[1][tid][129] = 0.f;
    }
    // ---- stage weights for CPG channels ----
    for (int j = tid; j < CPG * 36; j += 256) {
        int cj = j / 36, t = j % 36;
        swp[cj][t] = wp[(4 * (c0 + cj) + 2 * dy) * 18 + t];
    }
    __syncthreads();

    const int rr  = tid >> 5;         // output rows 2rr, 2rr+1
    const int w0c = (tid & 31) * 4;

    // ---- hoist mask window into registers: mr[r][parity][0..5] ----
    float mr[4][2][6];
    #pragma unroll
    for (int r = 0; r < 4; r++) {
        const int sr = 2 * rr + r;
        float4 a0 = *(const float4*)&smm[0][sr][w0c];
        float2 b0 = *(const float2*)&smm[0][sr][w0c + 4];
        float4 a1 = *(const float4*)&smm[1][sr][w0c];
        float2 b1 = *(const float2*)&smm[1][sr][w0c + 4];
        mr[r][0][0] = a0.x; mr[r][0][1] = a0.y; mr[r][0][2] = a0.z;
        mr[r][0][3] = a0.w; mr[r][0][4] = b0.x; mr[r][0][5] = b0.y;
        mr[r][1][0] = a1.x; mr[r][1][1] = a1.y; mr[r][1][2] = a1.z;
        mr[r][1][3] = a1.w; mr[r][1][4] = b1.x; mr[r][1][5] = b1.y;
    }

    for (int cj = 0; cj < CPG; cj++) {
        const int c = c0 + cj;
        __syncthreads();   // previous iteration's reads of sy are done
        // ---- stage y tile for channel c ----
        for (int idx = tid; idx < 18 * 64; idx += 256) {
            int r  = idx >> 6;
            int q2 = (idx & 63) * 2;
            int gy = 2 * (hb - 1 + r) + dy;
            uint2 yv = make_uint2(0u, 0u);
            if ((unsigned)gy < (unsigned)HH)
                yv = *(const uint2*)
                    &g_yh[((size_t)(b * CMID + c) * HH + gy) * 128 + q2];
            float2 f0 = h2f2(yv.x), f1 = h2f2(yv.y);
            sy[0][r][1 + q2] = f0.x; sy[1][r][1 + q2] = f0.y;
            sy[0][r][2 + q2] = f1.x; sy[1][r][2 + q2] = f1.y;
        }
        __syncthreads();

        float a[2][2][4];
        #pragma unroll
        for (int o = 0; o < 2; o++)
            #pragma unroll
            for (int gx = 0; gx < 2; gx++)
                #pragma unroll
                for (int p = 0; p < 4; p++)
                    a[o][gx][p] = 0.f;

        #pragma unroll
        for (int r = 0; r < 4; r++) {
            const int sr = 2 * rr + r;
            float4 ya0 = *(const float4*)&sy[0][sr][w0c];
            float2 yb0 = *(const float2*)&sy[0][sr][w0c + 4];
            float4 ya1 = *(const float4*)&sy[1][sr][w0c];
            float2 yb1 = *(const float2*)&sy[1][sr][w0c + 4];
            float yv0[6] = {ya0.x, ya0.y, ya0.z, ya0.w, yb0.x, yb0.y};
            float yv1[6] = {ya1.x, ya1.y, ya1.z, ya1.w, yb1.x, yb1.y};

            #pragma unroll
            for (int orow = 0; orow < 2; orow++) {
                const int kh = r - orow;
                if (kh < 0 || kh > 2) continue;
                #pragma unroll
                for (int kw = 0; kw < 3; kw++) {
                    float wy0 = swp[cj][kh * 3 + kw];
                    float wm0 = swp[cj][9 + kh * 3 + kw];
                    float wy1 = swp[cj][18 + kh * 3 + kw];
                    float wm1 = swp[cj][27 + kh * 3 + kw];
                    #pragma unroll
                    for (int p = 0; p < 4; p++) {
                        a[orow][0][p] = fmaf(wy0, yv0[kw + p], a[orow][0][p]);
                        a[orow][0][p] = fmaf(wm0, mr[r][0][kw + p], a[orow][0][p]);
                        a[orow][1][p] = fmaf(wy1, yv1[kw + p], a[orow][1][p]);
                        a[orow][1][p] = fmaf(wm1, mr[r][1][kw + p], a[orow][1][p]);
                    }
                }
            }
        }

        const int g0 = 4 * c + 2 * dy;
        #pragma unroll
        for (int orow = 0; orow < 2; orow++) {
            const int h = hb + 2 * rr + orow;
            *(float4*)&out[((size_t)(b * CO + g0) * H2 + h) * W2 + w0c] =
                make_float4(a[orow][0][0], a[orow][0][1],
                            a[orow][0][2], a[orow][0][3]);
            *(float4*)&out[((size_t)(b * CO + g0 + 1) * H2 + h) * W2 + w0c] =
                make_float4(a[orow][1][0], a[orow][1][1],
                            a[orow][1][2], a[orow][1][3]);
        }
    }
}

// ---------------------------------------------------------------------------
extern "C" void kernel_launch(void* const* d_in, const int* in_sizes, int n_in,
                              void* d_out, int out_size)
{
    const float* x      = (const float*)d_in[0];
    const float* mask   = (const float*)d_in[1];
    const float* w_body = (const float*)d_in[2];
    const float* w_proj = (const float*)d_in[3];
    float* out = (float*)d_out;

    cudaFuncSetAttribute(conv1_mma_kernel,
                         cudaFuncAttributeMaxDynamicSharedMemorySize, SMEM_SZ);

    prep_kernel<<<(WN + PX_N + 255) / 256, 256>>>(x, w_body);

    dim3 g1(WW / 128, HH / 4, B_);          // (2, 64, 8) = 1024 CTAs
    conv1_mma_kernel<<<g1, 256, SMEM_SZ>>>();

    dim3 g2(H2 / 16, 2 * (CMID / CPG), B_); // (8, 16, 8) = 1024 CTAs
    conv2_kernel<<<g2, 256>>>(mask, w_proj, out);
}

// round 9
// speedup vs baseline: 1.0455x; 1.0455x over previous
#include <cuda_runtime.h>
#include <cstdint>

#define B_   8
#define CIN  96
#define CMID 48
#define HH   256
#define WW   256
#define H2   128
#define W2   128
#define CO   192

// conv1 output y in fp16: [b][oc][h][w], stored as half2 (adjacent pixels). 50 MB.
__device__ unsigned g_yh[B_ * CMID * HH * WW / 2];
// Pre-packed fp16 weights: [chunk6][tap9][icp8][oc48] half2 (lo = even ic)
__device__ unsigned g_wph[6 * 9 * 8 * 48];

__device__ __forceinline__ unsigned pack_h2(float lo, float hi) {
    unsigned r;
    asm("{ .reg .b16 l, h; cvt.rn.f16.f32 l, %1; cvt.rn.f16.f32 h, %2; "
        "mov.b32 %0, {l, h}; }" : "=r"(r) : "f"(lo), "f"(hi));
    return r;
}
__device__ __forceinline__ float2 h2f2(unsigned h) {
    float2 f;
    asm("{ .reg .b16 l, h; mov.b32 {l, h}, %2; "
        "cvt.f32.f16 %0, l; cvt.f32.f16 %1, h; }"
        : "=f"(f.x), "=f"(f.y) : "r"(h));
    return f;
}

__device__ __forceinline__ void mma_f16(float* c,
    unsigned a0, unsigned a1, unsigned a2, unsigned a3,
    unsigned b0, unsigned b1)
{
    asm volatile(
        "mma.sync.aligned.m16n8k16.row.col.f32.f16.f16.f32 "
        "{%0,%1,%2,%3}, {%4,%5,%6,%7}, {%8,%9}, {%0,%1,%2,%3};"
        : "+f"(c[0]), "+f"(c[1]), "+f"(c[2]), "+f"(c[3])
        : "r"(a0), "r"(a1), "r"(a2), "r"(a3), "r"(b0), "r"(b1));
}

__device__ __forceinline__ uint32_t smem_u32(const void* p) {
    uint32_t a;
    asm("{ .reg .u64 t; cvta.to.shared.u64 t, %1; cvt.u32.u64 %0, t; }"
        : "=r"(a) : "l"(p));
    return a;
}
#define CP_ASYNC16(dst, src) \
    asm volatile("cp.async.cg.shared.global [%0], [%1], 16;" \
                 :: "r"(dst), "l"(src))
#define CP_COMMIT() asm volatile("cp.async.commit_group;" ::: "memory")
#define CP_WAIT0()  asm volatile("cp.async.wait_group 0;" ::: "memory")

// ---------------------------------------------------------------------------
// Prepass (tiny): w_body[oc48][ic96][tap9] -> g_wph[chunk][tap][icp][oc] half2
// ---------------------------------------------------------------------------
#define WN (6 * 9 * 8 * 48)
__global__ void prep_w_kernel(const float* __restrict__ w)
{
    int i = blockIdx.x * 256 + threadIdx.x;
    if (i >= WN) return;
    int chunk = i / 3456;
    int r  = i % 3456;
    int tap = r / 384;
    int r2  = r % 384;
    int icp = r2 / 48;
    int oc  = r2 % 48;
    int ic  = chunk * 16 + icp * 2;
    g_wph[i] = pack_h2(w[(oc * 96 + ic) * 9 + tap],
                       w[(oc * 96 + ic + 1) * 9 + tap]);
}

// ---------------------------------------------------------------------------
// conv1: fp16 m16n8k16 implicit GEMM, reads fp32 x directly.
// CTA: 256 thr / 8 warps. Tile: 512 pixels (4 rows x 128 cols) x 48 oc.
// Pipeline per 16-ic chunk: cp.async fp32 -> in-kernel convert to half2 smem
// -> mma. fp32 staging single-buffered (freed by convert), weights double.
// fp32 stage layout: [ic16][row6][136 cols], col i <-> x col (w0-4+i).
// ---------------------------------------------------------------------------
#define F32_FLOATS (16 * 6 * 136)   // 13056
#define XS_WORDS   (8 * 6 * 132)    // 6336 half2
#define WS_WORDS   (9 * 8 * 56)     // 4032 half2
#define SMEM_SZ    ((F32_FLOATS + XS_WORDS + 2 * WS_WORDS) * 4)  // 109824

__global__ __launch_bounds__(256, 2) void conv1_mma_kernel(
    const float* __restrict__ x)
{
    extern __shared__ unsigned sm[];
    float*    fs  = (float*)sm;                     // fp32 staging
    unsigned* xs  = sm + F32_FLOATS;                // half2 tile (single buf)
    unsigned* ws0 = sm + F32_FLOATS + XS_WORDS;     // 2 x WS_WORDS

    const int tid  = threadIdx.x;
    const int lane = tid & 31;
    const int wid  = tid >> 5;
    const int g    = lane >> 2;
    const int u    = lane & 3;

    const int w0 = blockIdx.x * 128;
    const int h0 = blockIdx.y * 4;
    const int b  = blockIdx.z;

    const int wrow  = wid >> 1;
    const int wcolb = (wid & 1) * 64;

    const uint32_t fs_sm = smem_u32(fs);
    const uint32_t ws_sm = smem_u32(ws0);

    // cp.async uint4 index range within a row (edges excluded: those 16B
    // segments would read outside the tensor and are fully masked anyway).
    const int jlo = (w0 == 0) ? 1 : 0;
    const int jhi = (w0 == 0) ? 34 : 33;

    auto issue_x = [&](int chunk) {
        // 96 rows (16 ic x 6), warp wid owns rows wid, wid+8, ...
        #pragma unroll
        for (int k = 0; k < 12; k++) {
            int rowid = wid + k * 8;
            int ic = rowid / 6, r = rowid - ic * 6;
            int gr = h0 - 1 + r;
            if ((unsigned)gr >= (unsigned)HH) continue;
            const float* src =
                x + ((size_t)((b * CIN + chunk * 16 + ic) * HH + gr)) * WW
                  + (w0 - 4);
            uint32_t dst = fs_sm + (rowid * 136) * 4;
            for (int q = lane; q < 34; q += 32)
                if (q >= jlo && q < jhi)
                    CP_ASYNC16(dst + q * 16, src + q * 4);
        }
    };
    auto issue_w = [&](int chunk, int buf) {
        const unsigned* wsrc = g_wph + chunk * 3456;
        uint32_t wd = ws_sm + buf * WS_WORDS * 4;
        for (int j = lane; j < 108; j += 32) {
            int rr = wid * 9 + j / 12, q = j % 12;
            CP_ASYNC16(wd + (rr * 56 + q * 4) * 4, wsrc + rr * 48 + q * 4);
        }
    };
    auto convert = [&]() {
        // 48 (icp, r) combos; warp wid owns combos wid, wid+8, ...
        #pragma unroll
        for (int k = 0; k < 6; k++) {
            int co = wid + k * 8;
            int icp = co / 6, r = co - icp * 6;
            bool rok = ((unsigned)(h0 - 1 + r) < (unsigned)HH);
            const float* s0 = fs + (icp * 12 + r) * 136 + 3;
            const float* s1 = s0 + 816;   // +6*136 (next ic)
            unsigned* d = xs + co * 132;  // (icp*6 + r) * 132
            for (int c = lane; c < 132; c += 32) {
                float f0 = s0[c], f1 = s1[c];
                bool ok = rok && ((unsigned)(w0 - 1 + c) < (unsigned)WW);
                if (!ok) { f0 = 0.f; f1 = 0.f; }
                d[c] = pack_h2(f0, f1);
            }
        }
    };

    float acc[4][6][4];
    #pragma unroll
    for (int t = 0; t < 4; t++)
        #pragma unroll
        for (int n = 0; n < 6; n++)
            #pragma unroll
            for (int k = 0; k < 4; k++)
                acc[t][n][k] = 0.f;

    issue_x(0);
    issue_w(0, 0);
    CP_COMMIT();

    for (int chunk = 0; chunk < 6; chunk++) {
        const int buf = chunk & 1;
        CP_WAIT0();
        __syncthreads();          // data arrived; prev compute done with xs
        convert();
        __syncthreads();          // xs ready; fs free for next chunk
        if (chunk < 5) {
            issue_x(chunk + 1);
            issue_w(chunk + 1, buf ^ 1);
            CP_COMMIT();
        }

        const unsigned* wsb = ws0 + buf * WS_WORDS;
        #pragma unroll
        for (int tap = 0; tap < 9; tap++) {
            const int kh = tap / 3, kw = tap % 3;
            const int xr = wrow + kh;

            unsigned bf[6][2];
            #pragma unroll
            for (int n = 0; n < 6; n++) {
                bf[n][0] = wsb[(tap * 8 + u) * 56 + n * 8 + g];
                bf[n][1] = wsb[(tap * 8 + u + 4) * 56 + n * 8 + g];
            }
            #pragma unroll
            for (int t = 0; t < 4; t++) {
                const int colc = wcolb + t * 16 + g + kw;
                unsigned a0 = xs[(u * 6 + xr) * 132 + colc];
                unsigned a1 = xs[(u * 6 + xr) * 132 + colc + 8];
                unsigned a2 = xs[((u + 4) * 6 + xr) * 132 + colc];
                unsigned a3 = xs[((u + 4) * 6 + xr) * 132 + colc + 8];
                #pragma unroll
                for (int n = 0; n < 6; n++)
                    mma_f16(acc[t][n], a0, a1, a2, a3, bf[n][0], bf[n][1]);
            }
        }
    }

    // ---- store D as fp16 half2 (pair lanes g, g^1 = adjacent pixels) ----
    #pragma unroll
    for (int t = 0; t < 4; t++) {
        const int p0 = wid * 64 + t * 16 + g;
        const int h  = h0 + (p0 >> 7);
        const int hc = ((w0 + (p0 & 127)) >> 1);
        #pragma unroll
        for (int n = 0; n < 6; n++) {
            const int oc = n * 8 + 2 * u;
            float q0 = __shfl_xor_sync(0xffffffffu, acc[t][n][0], 4);
            float q1 = __shfl_xor_sync(0xffffffffu, acc[t][n][1], 4);
            float q2 = __shfl_xor_sync(0xffffffffu, acc[t][n][2], 4);
            float q3 = __shfl_xor_sync(0xffffffffu, acc[t][n][3], 4);
            if (!(g & 1)) {
                unsigned* base =
                    g_yh + ((size_t)(b * CMID + oc) * HH + h) * 128 + hc;
                base[0]                       = pack_h2(acc[t][n][0], q0);
                base[(size_t)HH * WW / 2]     = pack_h2(acc[t][n][1], q1);
                base[4]                       = pack_h2(acc[t][n][2], q2);
                base[(size_t)HH * WW / 2 + 4] = pack_h2(acc[t][n][3], q3);
            }
        }
    }
}

// ---------------------------------------------------------------------------
// Kernel B (reverted to round-7 version, 55us): fused pixel_unshuffle +
// mask interleave + grouped 3x3 conv. CTA: 16 rows x 128 cols, thread 2x4.
// ---------------------------------------------------------------------------
__global__ __launch_bounds__(256) void conv2_kernel(
    const float* __restrict__ mask, const float* __restrict__ wp,
    float* __restrict__ out)
{
    __shared__ __align__(16) float sy[2][18][132];
    __shared__ __align__(16) float smm[2][18][132];
    __shared__ float swp[36];

    const int tid = threadIdx.x;
    const int hb  = blockIdx.x * 16;
    const int gp  = blockIdx.y;     // (c, dy)
    const int b   = blockIdx.z;
    const int c   = gp >> 1;
    const int dy  = gp & 1;
    const int g0  = 4 * c + 2 * dy;

    if (tid < 36) swp[tid] = wp[g0 * 18 + tid];

    #pragma unroll
    for (int it = 0; it < 5; it++) {
        int idx = it * 256 + tid;
        if (idx < 1152) {
            int r  = idx >> 6;
            int q2 = (idx & 63) * 2;
            int gy = 2 * (hb - 1 + r) + dy;
            uint2 yv = make_uint2(0u, 0u);
            float4 mv = make_float4(0.f, 0.f, 0.f, 0.f);
            if ((unsigned)gy < (unsigned)HH) {
                yv = *(const uint2*)&g_yh[((size_t)(b * CMID + c) * HH + gy) * 128 + q2];
                mv = *(const float4*)&mask[((size_t)(b * HH) + gy) * WW + 2 * q2];
            }
            float2 f0 = h2f2(yv.x), f1 = h2f2(yv.y);
            sy[0][r][1 + q2] = f0.x;  sy[1][r][1 + q2] = f0.y;
            sy[0][r][2 + q2] = f1.x;  sy[1][r][2 + q2] = f1.y;
            smm[0][r][1 + q2] = mv.x; smm[1][r][1 + q2] = mv.y;
            smm[0][r][2 + q2] = mv.z; smm[1][r][2 + q2] = mv.w;
        }
    }
    if (tid < 18) {
        sy[0][tid][0] = 0.f;   sy[1][tid][0] = 0.f;
        sy[0][tid][129] = 0.f; sy[1][tid][129] = 0.f;
        smm[0][tid][0] = 0.f;   smm[1][tid][0] = 0.f;
        smm[0][tid][129] = 0.f; smm[1][tid][129] = 0.f;
    }
    __syncthreads();

    const int rr  = tid >> 5;
    const int w0c = (tid & 31) * 4;

    float a[2][2][4];
    #pragma unroll
    for (int o = 0; o < 2; o++)
        #pragma unroll
        for (int gx = 0; gx < 2; gx++)
            #pragma unroll
            for (int p = 0; p < 4; p++)
                a[o][gx][p] = 0.f;

    #pragma unroll
    for (int r = 0; r < 4; r++) {
        const int sr = 2 * rr + r;
        float4 ya0 = *(const float4*)&sy[0][sr][w0c];
        float2 yb0 = *(const float2*)&sy[0][sr][w0c + 4];
        float4 ya1 = *(const float4*)&sy[1][sr][w0c];
        float2 yb1 = *(const float2*)&sy[1][sr][w0c + 4];
        float4 ma0 = *(const float4*)&smm[0][sr][w0c];
        float2 mb0 = *(const float2*)&smm[0][sr][w0c + 4];
        float4 ma1 = *(const float4*)&smm[1][sr][w0c];
        float2 mb1 = *(const float2*)&smm[1][sr][w0c + 4];
        float yv0[6] = {ya0.x, ya0.y, ya0.z, ya0.w, yb0.x, yb0.y};
        float yv1[6] = {ya1.x, ya1.y, ya1.z, ya1.w, yb1.x, yb1.y};
        float mv0[6] = {ma0.x, ma0.y, ma0.z, ma0.w, mb0.x, mb0.y};
        float mv1[6] = {ma1.x, ma1.y, ma1.z, ma1.w, mb1.x, mb1.y};

        #pragma unroll
        for (int orow = 0; orow < 2; orow++) {
            const int kh = r - orow;
            if (kh < 0 || kh > 2) continue;
            #pragma unroll
            for (int kw = 0; kw < 3; kw++) {
                float wy0 = swp[kh * 3 + kw];
                float wm0 = swp[9 + kh * 3 + kw];
                float wy1 = swp[18 + kh * 3 + kw];
                float wm1 = swp[27 + kh * 3 + kw];
                #pragma unroll
                for (int p = 0; p < 4; p++) {
                    a[orow][0][p] = fmaf(wy0, yv0[kw + p], a[orow][0][p]);
                    a[orow][0][p] = fmaf(wm0, mv0[kw + p], a[orow][0][p]);
                    a[orow][1][p] = fmaf(wy1, yv1[kw + p], a[orow][1][p]);
                    a[orow][1][p] = fmaf(wm1, mv1[kw + p], a[orow][1][p]);
                }
            }
        }
    }

    #pragma unroll
    for (int orow = 0; orow < 2; orow++) {
        const int h = hb + 2 * rr + orow;
        *(float4*)&out[((size_t)(b * CO + g0) * H2 + h) * W2 + w0c] =
            make_float4(a[orow][0][0], a[orow][0][1], a[orow][0][2], a[orow][0][3]);
        *(float4*)&out[((size_t)(b * CO + g0 + 1) * H2 + h) * W2 + w0c] =
            make_float4(a[orow][1][0], a[orow][1][1], a[orow][1][2], a[orow][1][3]);
    }
}

// ---------------------------------------------------------------------------
extern "C" void kernel_launch(void* const* d_in, const int* in_sizes, int n_in,
                              void* d_out, int out_size)
{
    const float* x      = (const float*)d_in[0];
    const float* mask   = (const float*)d_in[1];
    const float* w_body = (const float*)d_in[2];
    const float* w_proj = (const float*)d_in[3];
    float* out = (float*)d_out;

    cudaFuncSetAttribute(conv1_mma_kernel,
                         cudaFuncAttributeMaxDynamicSharedMemorySize, SMEM_SZ);

    prep_w_kernel<<<(WN + 255) / 256, 256>>>(w_body);

    dim3 g1(WW / 128, HH / 4, B_);      // (2, 64, 8) = 1024 CTAs
    conv1_mma_kernel<<<g1, 256, SMEM_SZ>>>(x);

    dim3 g2(H2 / 16, 96, B_);           // (8, 96, 8) = 6144 CTAs
    conv2_kernel<<<g2, 256>>>(mask, w_proj, out);
}

// round 11
// speedup vs baseline: 1.0985x; 1.0507x over previous
#include <cuda_runtime.h>
#include <cstdint>

#define B_   8
#define CIN  96
#define CMID 48
#define HH   256
#define WW   256
#define H2   128
#define W2   128
#define CO   192

// y fp16, column-parity de-interleaved: [b][oc][h][parity][w128] halves,
// stored as half2 (same-parity adjacent cols). Row = 128 uint. 50 MB.
__device__ unsigned g_yd[B_ * CMID * HH * 128];
// Pre-packed fp16 weights: [chunk6][tap9][icp8][oc48] half2 (lo = even ic)
__device__ unsigned g_wph[6 * 9 * 8 * 48];
// Pre-packed, pre-padded fp16 x: [b][icp48][row 258][col 264] half2. ~105 MB.
#define XPR 258
#define XPC 264
__device__ unsigned g_xh[B_ * 48 * XPR * XPC];
// Mask de-interleaved: [b][dy][r128][parity][q128] fp32. 2 MB.
__device__ float g_m2[B_ * 2 * 128 * 256];

__device__ __forceinline__ unsigned pack_h2(float lo, float hi) {
    unsigned r;
    asm("{ .reg .b16 l, h; cvt.rn.f16.f32 l, %1; cvt.rn.f16.f32 h, %2; "
        "mov.b32 %0, {l, h}; }" : "=r"(r) : "f"(lo), "f"(hi));
    return r;
}
__device__ __forceinline__ float2 h2f2(unsigned h) {
    float2 f;
    asm("{ .reg .b16 l, h; mov.b32 {l, h}, %2; "
        "cvt.f32.f16 %0, l; cvt.f32.f16 %1, h; }"
        : "=f"(f.x), "=f"(f.y) : "r"(h));
    return f;
}

__device__ __forceinline__ void mma_f16(float* c,
    unsigned a0, unsigned a1, unsigned a2, unsigned a3,
    unsigned b0, unsigned b1)
{
    asm volatile(
        "mma.sync.aligned.m16n8k16.row.col.f32.f16.f16.f32 "
        "{%0,%1,%2,%3}, {%4,%5,%6,%7}, {%8,%9}, {%0,%1,%2,%3};"
        : "+f"(c[0]), "+f"(c[1]), "+f"(c[2]), "+f"(c[3])
        : "r"(a0), "r"(a1), "r"(a2), "r"(a3), "r"(b0), "r"(b1));
}

__device__ __forceinline__ uint32_t smem_u32(const void* p) {
    uint32_t a;
    asm("{ .reg .u64 t; cvta.to.shared.u64 t, %1; cvt.u32.u64 %0, t; }"
        : "=r"(a) : "l"(p));
    return a;
}
#define CP_ASYNC16(dst, src) \
    asm volatile("cp.async.cg.shared.global [%0], [%1], 16;" \
                 :: "r"(dst), "l"(src))
#define CP_COMMIT() asm volatile("cp.async.commit_group;" ::: "memory")
#define CP_WAIT1()  asm volatile("cp.async.wait_group 1;" ::: "memory")
#define CP_WAIT0()  asm volatile("cp.async.wait_group 0;" ::: "memory")

// ---------------------------------------------------------------------------
// Fused prepass: weights, x relayout, mask de-interleave.
// ---------------------------------------------------------------------------
#define WN   (6 * 9 * 8 * 48)
#define PX_N (B_ * 48 * XPR * (XPC / 4))
#define MN   (B_ * 2 * 128 * 16)

__global__ void prep_kernel(const float* __restrict__ x,
                            const float* __restrict__ w,
                            const float* __restrict__ mask)
{
    int i = blockIdx.x * 256 + threadIdx.x;
    if (i < WN) {
        int chunk = i / 3456;
        int r  = i % 3456;
        int tap = r / 384;
        int r2  = r % 384;
        int icp = r2 / 48;
        int oc  = r2 % 48;
        int ic  = chunk * 16 + icp * 2;
        g_wph[i] = pack_h2(w[(oc * 96 + ic) * 9 + tap],
                           w[(oc * 96 + ic + 1) * 9 + tap]);
        return;
    }
    i -= WN;
    if (i < PX_N) {
        int pc0 = (i % (XPC / 4)) * 4;
        int t   = i / (XPC / 4);
        int pr  = t % XPR;
        int t2  = t / XPR;
        int icp = t2 % 48;
        int b   = t2 / 48;
        int gr  = pr - 1;
        const float* s0 = x + ((size_t)((b * CIN + icp * 2) * HH + gr)) * WW;
        const float* s1 = s0 + (size_t)HH * WW;
        bool rok = ((unsigned)gr < (unsigned)HH);
        unsigned res[4];
        #pragma unroll
        for (int j = 0; j < 4; j++) {
            int ww = pc0 + j - 1;
            bool ok = rok && ((unsigned)ww < (unsigned)WW);
            float f0 = ok ? s0[ww] : 0.f;
            float f1 = ok ? s1[ww] : 0.f;
            res[j] = pack_h2(f0, f1);
        }
        *(uint4*)&g_xh[((size_t)(b * 48 + icp) * XPR + pr) * XPC + pc0] =
            *(uint4*)res;
        return;
    }
    i -= PX_N;
    if (i >= MN) return;
    int k16 = (i & 15) * 16;
    int r   = (i >> 4) & 127;
    int dy  = (i >> 11) & 1;
    int b   = i >> 12;
    const float* src = mask + ((size_t)(b * HH) + 2 * r + dy) * WW + k16;
    float4 v0 = *(const float4*)&src[0];
    float4 v1 = *(const float4*)&src[4];
    float4 v2 = *(const float4*)&src[8];
    float4 v3 = *(const float4*)&src[12];
    float* dst = g_m2 + (((size_t)(b * 2 + dy) * 128 + r) * 256);
    int q0 = k16 / 2;
    *(float4*)&dst[q0]           = make_float4(v0.x, v0.z, v1.x, v1.z);
    *(float4*)&dst[128 + q0]     = make_float4(v0.y, v0.w, v1.y, v1.w);
    *(float4*)&dst[q0 + 4]       = make_float4(v2.x, v2.z, v3.x, v3.z);
    *(float4*)&dst[128 + q0 + 4] = make_float4(v2.y, v2.w, v3.y, v3.w);
}

// ---------------------------------------------------------------------------
// conv1 via mma.sync fp16 m16n8k16, cp.async double-buffered pipeline.
// (R7 mainloop; epilogue writes parity-de-interleaved fp16 y)
// ---------------------------------------------------------------------------
#define XS_WORDS (8 * 6 * 132)   // 6336
#define WS_WORDS (9 * 8 * 56)    // 4032
#define SMEM_SZ  ((2 * XS_WORDS + 2 * WS_WORDS) * 4)

__global__ __launch_bounds__(256) void conv1_mma_kernel()
{
    extern __shared__ unsigned sm[];
    unsigned* xs0 = sm;
    unsigned* ws0 = sm + 2 * XS_WORDS;

    const int tid  = threadIdx.x;
    const int lane = tid & 31;
    const int wid  = tid >> 5;
    const int g    = lane >> 2;
    const int u    = lane & 3;

    const int w0 = blockIdx.x * 128;
    const int h0 = blockIdx.y * 4;
    const int b  = blockIdx.z;

    const int wrow  = wid >> 1;
    const int wcolb = (wid & 1) * 64;

    const uint32_t xs_sm = smem_u32(xs0);
    const uint32_t ws_sm = smem_u32(ws0);

    auto issue = [&](int chunk, int buf) {
        const unsigned* srcp =
            g_xh + ((size_t)(b * 48 + chunk * 8 + wid) * XPR + h0) * XPC + w0;
        uint32_t xd = xs_sm + (buf * XS_WORDS + wid * (6 * 132)) * 4;
        for (int j = lane; j < 198; j += 32) {
            int r = j / 33, q = j - r * 33;
            CP_ASYNC16(xd + (r * 132 + q * 4) * 4,
                       srcp + (size_t)r * XPC + q * 4);
        }
        const unsigned* wsrc = g_wph + chunk * 3456;
        uint32_t wd = ws_sm + buf * WS_WORDS * 4;
        for (int j = lane; j < 108; j += 32) {
            int rr = wid * 9 + j / 12, q = j % 12;
            CP_ASYNC16(wd + (rr * 56 + q * 4) * 4, wsrc + rr * 48 + q * 4);
        }
    };

    float acc[4][6][4];
    #pragma unroll
    for (int t = 0; t < 4; t++)
        #pragma unroll
        for (int n = 0; n < 6; n++)
            #pragma unroll
            for (int k = 0; k < 4; k++)
                acc[t][n][k] = 0.f;

    issue(0, 0);
    CP_COMMIT();

    for (int chunk = 0; chunk < 6; chunk++) {
        const int buf = chunk & 1;
        if (chunk < 5) {
            issue(chunk + 1, buf ^ 1);
            CP_COMMIT();
            CP_WAIT1();
        } else {
            CP_WAIT0();
        }
        __syncthreads();

        const unsigned* xsb = xs0 + buf * XS_WORDS;
        const unsigned* wsb = ws0 + buf * WS_WORDS;

        #pragma unroll
        for (int tap = 0; tap < 9; tap++) {
            const int kh = tap / 3, kw = tap % 3;
            const int xr = wrow + kh;

            unsigned bf[6][2];
            #pragma unroll
            for (int n = 0; n < 6; n++) {
                bf[n][0] = wsb[(tap * 8 + u) * 56 + n * 8 + g];
                bf[n][1] = wsb[(tap * 8 + u + 4) * 56 + n * 8 + g];
            }
            #pragma unroll
            for (int t = 0; t < 4; t++) {
                const int colc = wcolb + t * 16 + g + kw;
                unsigned a0 = xsb[(u * 6 + xr) * 132 + colc];
                unsigned a1 = xsb[(u * 6 + xr) * 132 + colc + 8];
                unsigned a2 = xsb[((u + 4) * 6 + xr) * 132 + colc];
                unsigned a3 = xsb[((u + 4) * 6 + xr) * 132 + colc + 8];
                #pragma unroll
                for (int n = 0; n < 6; n++)
                    mma_f16(acc[t][n], a0, a1, a2, a3, bf[n][0], bf[n][1]);
            }
        }
        __syncthreads();
    }

    // ---- store y parity-de-interleaved: pair lanes g, g^2 => lane ^ 8 ----
    #pragma unroll
    for (int t = 0; t < 4; t++) {
        const int p0   = wid * 64 + t * 16 + g;
        const int h    = h0 + (p0 >> 7);
        const int par  = g & 1;
        const int hidx = ((p0 & 127) >> 2) + (w0 >> 2);
        #pragma unroll
        for (int n = 0; n < 6; n++) {
            const int oc = n * 8 + 2 * u;
            float q0 = __shfl_xor_sync(0xffffffffu, acc[t][n][0], 8);
            float q1 = __shfl_xor_sync(0xffffffffu, acc[t][n][1], 8);
            float q2 = __shfl_xor_sync(0xffffffffu, acc[t][n][2], 8);
            float q3 = __shfl_xor_sync(0xffffffffu, acc[t][n][3], 8);
            if (!(g & 2)) {
                unsigned* base =
                    g_yd + ((size_t)(b * CMID + oc) * HH + h) * 128
                         + par * 64 + hidx;
                base[0]            = pack_h2(acc[t][n][0], q0);
                base[HH * 128]     = pack_h2(acc[t][n][1], q1);
                base[2]            = pack_h2(acc[t][n][2], q2);
                base[HH * 128 + 2] = pack_h2(acc[t][n][3], q3);
            }
        }
    }
}

// ---------------------------------------------------------------------------
// conv2 v4: vectorized staging from de-interleaved y + mask; window edges
// via warp shuffles. CTA: 16 out rows x 128 cols, thread = 2 rows x 4 cols.
// smem rows: data cols [0..127], zero pad [128..131].
// ---------------------------------------------------------------------------
__device__ __forceinline__ void win6(float out[6], const float* row,
                                     int w0c, int lane)
{
    float4 a4 = *(const float4*)&row[w0c];
    float lm = __shfl_up_sync(0xffffffffu, a4.w, 1);
    float rs = __shfl_down_sync(0xffffffffu, a4.x, 1);
    if (lane == 0)  lm = 0.f;
    if (lane == 31) rs = 0.f;
    out[0] = lm;   out[1] = a4.x; out[2] = a4.y;
    out[3] = a4.z; out[4] = a4.w; out[5] = rs;
}

__global__ __launch_bounds__(256) void conv2_kernel(
    const float* __restrict__ wp, float* __restrict__ out)
{
    __shared__ __align__(16) float sy[2][18][132];
    __shared__ __align__(16) float smm[2][18][132];
    __shared__ float swp[36];

    const int tid = threadIdx.x;
    const int hb  = blockIdx.x * 16;
    const int gp  = blockIdx.y;     // (c, dy)
    const int b   = blockIdx.z;
    const int c   = gp >> 1;
    const int dy  = gp & 1;
    const int g0  = 4 * c + 2 * dy;

    if (tid < 36) swp[tid] = wp[g0 * 18 + tid];
    if (tid < 36) {   // zero pads: 2 par x 18 rows
        int p = tid & 1, r = tid >> 1;
        *(float4*)&sy[p][r][128]  = make_float4(0.f, 0.f, 0.f, 0.f);
        *(float4*)&smm[p][r][128] = make_float4(0.f, 0.f, 0.f, 0.f);
    }

    // ---- stage y: 576 slots (18r x 2p x 16), uint4 -> 2x float4 STS ----
    for (int idx = tid; idx < 576; idx += 256) {
        int r   = idx / 32;
        int rem = idx & 31;
        int p   = rem >> 4;
        int k8  = (rem & 15) * 8;
        int gy  = 2 * (hb - 1 + r) + dy;
        uint4 yv = make_uint4(0u, 0u, 0u, 0u);
        if ((unsigned)gy < (unsigned)HH)
            yv = *(const uint4*)
                &g_yd[((size_t)(b * CMID + c) * HH + gy) * 128 + p * 64 + k8 / 2];
        float2 f0 = h2f2(yv.x), f1 = h2f2(yv.y);
        float2 f2 = h2f2(yv.z), f3 = h2f2(yv.w);
        *(float4*)&sy[p][r][k8]     = make_float4(f0.x, f0.y, f1.x, f1.y);
        *(float4*)&sy[p][r][k8 + 4] = make_float4(f2.x, f2.y, f3.x, f3.y);
    }
    // ---- stage mask: 1152 slots (18r x 2p x 32), float4 -> float4 ----
    for (int idx = tid; idx < 1152; idx += 256) {
        int r   = idx / 64;
        int rem = idx & 63;
        int p   = rem >> 5;
        int m4  = (rem & 31) * 4;
        int gy2 = hb - 1 + r;
        float4 mv = make_float4(0.f, 0.f, 0.f, 0.f);
        if ((unsigned)gy2 < 128u)
            mv = *(const float4*)
                &g_m2[(((size_t)(b * 2 + dy) * 128 + gy2) * 256) + p * 128 + m4];
        *(float4*)&smm[p][r][m4] = mv;
    }
    __syncthreads();

    const int rr   = tid >> 5;
    const int lane = tid & 31;
    const int w0c  = lane * 4;

    float a[2][2][4];
    #pragma unroll
    for (int o = 0; o < 2; o++)
        #pragma unroll
        for (int gx = 0; gx < 2; gx++)
            #pragma unroll
            for (int p = 0; p < 4; p++)
                a[o][gx][p] = 0.f;

    #pragma unroll
    for (int r = 0; r < 4; r++) {
        const int sr = 2 * rr + r;
        float yv0[6], yv1[6], mv0[6], mv1[6];
        win6(yv0, &sy[0][sr][0],  w0c, lane);
        win6(yv1, &sy[1][sr][0],  w0c, lane);
        win6(mv0, &smm[0][sr][0], w0c, lane);
        win6(mv1, &smm[1][sr][0], w0c, lane);

        #pragma unroll
        for (int orow = 0; orow < 2; orow++) {
            const int kh = r - orow;
            if (kh < 0 || kh > 2) continue;
            #pragma unroll
            for (int kw = 0; kw < 3; kw++) {
                float wy0 = swp[kh * 3 + kw];
                float wm0 = swp[9 + kh * 3 + kw];
                float wy1 = swp[18 + kh * 3 + kw];
                float wm1 = swp[27 + kh * 3 + kw];
                #pragma unroll
                for (int p = 0; p < 4; p++) {
                    a[orow][0][p] = fmaf(wy0, yv0[kw + p], a[orow][0][p]);
                    a[orow][0][p] = fmaf(wm0, mv0[kw + p], a[orow][0][p]);
                    a[orow][1][p] = fmaf(wy1, yv1[kw + p], a[orow][1][p]);
                    a[orow][1][p] = fmaf(wm1, mv1[kw + p], a[orow][1][p]);
                }
            }
        }
    }

    #pragma unroll
    for (int orow = 0; orow < 2; orow++) {
        const int h = hb + 2 * rr + orow;
        *(float4*)&out[((size_t)(b * CO + g0) * H2 + h) * W2 + w0c] =
            make_float4(a[orow][0][0], a[orow][0][1],
                        a[orow][0][2], a[orow][0][3]);
        *(float4*)&out[((size_t)(b * CO + g0 + 1) * H2 + h) * W2 + w0c] =
            make_float4(a[orow][1][0], a[orow][1][1],
                        a[orow][1][2], a[orow][1][3]);
    }
}

// ---------------------------------------------------------------------------
extern "C" void kernel_launch(void* const* d_in, const int* in_sizes, int n_in,
                              void* d_out, int out_size)
{
    const float* x      = (const float*)d_in[0];
    const float* mask   = (const float*)d_in[1];
    const float* w_body = (const float*)d_in[2];
    const float* w_proj = (const float*)d_in[3];
    float* out = (float*)d_out;

    cudaFuncSetAttribute(conv1_mma_kernel,
                         cudaFuncAttributeMaxDynamicSharedMemorySize, SMEM_SZ);

    prep_kernel<<<(WN + PX_N + MN + 255) / 256, 256>>>(x, w_body, mask);

    dim3 g1(WW / 128, HH / 4, B_);      // (2, 64, 8) = 1024 CTAs
    conv1_mma_kernel<<<g1, 256, SMEM_SZ>>>();

    dim3 g2(H2 / 16, 96, B_);           // (8, 96, 8) = 6144 CTAs
    conv2_kernel<<<g2, 256>>>(w_proj, out);
}

// round 12
// speedup vs baseline: 1.1882x; 1.0817x over previous
#include <cuda_runtime.h>
#include <cstdint>

#define B_   8
#define CIN  96
#define CMID 48
#define HH   256
#define WW   256
#define H2   128
#define W2   128
#define CO   192

// conv1 output y in fp16: [b][oc][h][w], stored as half2 (adjacent pixels). 50 MB.
__device__ unsigned g_yh[B_ * CMID * HH * WW / 2];
// Pre-packed fp16 weights: [chunk6][tap9][icp8][oc48] half2 (lo = even ic)
__device__ unsigned g_wph[6 * 9 * 8 * 48];
// Pre-packed, pre-padded fp16 x: [b][icp48][row 258][col 264] half2. ~105 MB.
#define XPR 258
#define XPC 264
__device__ unsigned g_xh[B_ * 48 * XPR * XPC];

__device__ __forceinline__ unsigned pack_h2(float lo, float hi) {
    unsigned r;
    asm("{ .reg .b16 l, h; cvt.rn.f16.f32 l, %1; cvt.rn.f16.f32 h, %2; "
        "mov.b32 %0, {l, h}; }" : "=r"(r) : "f"(lo), "f"(hi));
    return r;
}
__device__ __forceinline__ float2 h2f2(unsigned h) {
    float2 f;
    asm("{ .reg .b16 l, h; mov.b32 {l, h}, %2; "
        "cvt.f32.f16 %0, l; cvt.f32.f16 %1, h; }"
        : "=f"(f.x), "=f"(f.y) : "r"(h));
    return f;
}

__device__ __forceinline__ void mma_f16(float* c,
    unsigned a0, unsigned a1, unsigned a2, unsigned a3,
    unsigned b0, unsigned b1)
{
    asm volatile(
        "mma.sync.aligned.m16n8k16.row.col.f32.f16.f16.f32 "
        "{%0,%1,%2,%3}, {%4,%5,%6,%7}, {%8,%9}, {%0,%1,%2,%3};"
        : "+f"(c[0]), "+f"(c[1]), "+f"(c[2]), "+f"(c[3])
        : "r"(a0), "r"(a1), "r"(a2), "r"(a3), "r"(b0), "r"(b1));
}

__device__ __forceinline__ uint32_t smem_u32(const void* p) {
    uint32_t a;
    asm("{ .reg .u64 t; cvta.to.shared.u64 t, %1; cvt.u32.u64 %0, t; }"
        : "=r"(a) : "l"(p));
    return a;
}
#define CP_ASYNC16(dst, src) \
    asm volatile("cp.async.cg.shared.global [%0], [%1], 16;" \
                 :: "r"(dst), "l"(src))
#define CP_COMMIT() asm volatile("cp.async.commit_group;" ::: "memory")
#define CP_WAIT1()  asm volatile("cp.async.wait_group 1;" ::: "memory")
#define CP_WAIT0()  asm volatile("cp.async.wait_group 0;" ::: "memory")

// ---------------------------------------------------------------------------
// Fused prepass: weights then x relayout.
// ---------------------------------------------------------------------------
#define WN   (6 * 9 * 8 * 48)
#define PX_N (B_ * 48 * XPR * (XPC / 4))

__global__ void prep_kernel(const float* __restrict__ x,
                            const float* __restrict__ w)
{
    int i = blockIdx.x * 256 + threadIdx.x;
    if (i < WN) {
        int chunk = i / 3456;
        int r  = i % 3456;
        int tap = r / 384;
        int r2  = r % 384;
        int icp = r2 / 48;
        int oc  = r2 % 48;
        int ic  = chunk * 16 + icp * 2;
        g_wph[i] = pack_h2(w[(oc * 96 + ic) * 9 + tap],
                           w[(oc * 96 + ic + 1) * 9 + tap]);
        return;
    }
    i -= WN;
    if (i >= PX_N) return;
    int pc0 = (i % (XPC / 4)) * 4;
    int t   = i / (XPC / 4);
    int pr  = t % XPR;
    int t2  = t / XPR;
    int icp = t2 % 48;
    int b   = t2 / 48;
    int gr  = pr - 1;
    const float* s0 = x + ((size_t)((b * CIN + icp * 2) * HH + gr)) * WW;
    const float* s1 = s0 + (size_t)HH * WW;
    bool rok = ((unsigned)gr < (unsigned)HH);
    unsigned res[4];
    #pragma unroll
    for (int j = 0; j < 4; j++) {
        int ww = pc0 + j - 1;
        bool ok = rok && ((unsigned)ww < (unsigned)WW);
        float f0 = ok ? s0[ww] : 0.f;
        float f1 = ok ? s1[ww] : 0.f;
        res[j] = pack_h2(f0, f1);
    }
    *(uint4*)&g_xh[((size_t)(b * 48 + icp) * XPR + pr) * XPC + pc0] =
        *(uint4*)res;
}

// ---------------------------------------------------------------------------
// conv1 via mma.sync fp16 m16n8k16, cp.async double-buffered pipeline.
// R7 mainloop; ONLY change: __launch_bounds__(256, 2) to force 2 CTAs/SM.
// ---------------------------------------------------------------------------
#define XS_WORDS (8 * 6 * 132)   // 6336
#define WS_WORDS (9 * 8 * 56)    // 4032
#define SMEM_SZ  ((2 * XS_WORDS + 2 * WS_WORDS) * 4)

__global__ __launch_bounds__(256, 2) void conv1_mma_kernel()
{
    extern __shared__ unsigned sm[];
    unsigned* xs0 = sm;
    unsigned* ws0 = sm + 2 * XS_WORDS;

    const int tid  = threadIdx.x;
    const int lane = tid & 31;
    const int wid  = tid >> 5;
    const int g    = lane >> 2;
    const int u    = lane & 3;

    const int w0 = blockIdx.x * 128;
    const int h0 = blockIdx.y * 4;
    const int b  = blockIdx.z;

    const int wrow  = wid >> 1;
    const int wcolb = (wid & 1) * 64;

    const uint32_t xs_sm = smem_u32(xs0);
    const uint32_t ws_sm = smem_u32(ws0);

    auto issue = [&](int chunk, int buf) {
        const unsigned* srcp =
            g_xh + ((size_t)(b * 48 + chunk * 8 + wid) * XPR + h0) * XPC + w0;
        uint32_t xd = xs_sm + (buf * XS_WORDS + wid * (6 * 132)) * 4;
        for (int j = lane; j < 198; j += 32) {
            int r = j / 33, q = j - r * 33;
            CP_ASYNC16(xd + (r * 132 + q * 4) * 4,
                       srcp + (size_t)r * XPC + q * 4);
        }
        const unsigned* wsrc = g_wph + chunk * 3456;
        uint32_t wd = ws_sm + buf * WS_WORDS * 4;
        for (int j = lane; j < 108; j += 32) {
            int rr = wid * 9 + j / 12, q = j % 12;
            CP_ASYNC16(wd + (rr * 56 + q * 4) * 4, wsrc + rr * 48 + q * 4);
        }
    };

    float acc[4][6][4];
    #pragma unroll
    for (int t = 0; t < 4; t++)
        #pragma unroll
        for (int n = 0; n < 6; n++)
            #pragma unroll
            for (int k = 0; k < 4; k++)
                acc[t][n][k] = 0.f;

    issue(0, 0);
    CP_COMMIT();

    for (int chunk = 0; chunk < 6; chunk++) {
        const int buf = chunk & 1;
        if (chunk < 5) {
            issue(chunk + 1, buf ^ 1);
            CP_COMMIT();
            CP_WAIT1();
        } else {
            CP_WAIT0();
        }
        __syncthreads();

        const unsigned* xsb = xs0 + buf * XS_WORDS;
        const unsigned* wsb = ws0 + buf * WS_WORDS;

        #pragma unroll
        for (int tap = 0; tap < 9; tap++) {
            const int kh = tap / 3, kw = tap % 3;
            const int xr = wrow + kh;

            unsigned bf[6][2];
            #pragma unroll
            for (int n = 0; n < 6; n++) {
                bf[n][0] = wsb[(tap * 8 + u) * 56 + n * 8 + g];
                bf[n][1] = wsb[(tap * 8 + u + 4) * 56 + n * 8 + g];
            }
            #pragma unroll
            for (int t = 0; t < 4; t++) {
                const int colc = wcolb + t * 16 + g + kw;
                unsigned a0 = xsb[(u * 6 + xr) * 132 + colc];
                unsigned a1 = xsb[(u * 6 + xr) * 132 + colc + 8];
                unsigned a2 = xsb[((u + 4) * 6 + xr) * 132 + colc];
                unsigned a3 = xsb[((u + 4) * 6 + xr) * 132 + colc + 8];
                #pragma unroll
                for (int n = 0; n < 6; n++)
                    mma_f16(acc[t][n], a0, a1, a2, a3, bf[n][0], bf[n][1]);
            }
        }
        __syncthreads();
    }

    // ---- store y fp16 half2 (pair lanes g, g^1 = adjacent pixels) ----
    #pragma unroll
    for (int t = 0; t < 4; t++) {
        const int p0 = wid * 64 + t * 16 + g;
        const int h  = h0 + (p0 >> 7);
        const int hc = ((w0 + (p0 & 127)) >> 1);
        #pragma unroll
        for (int n = 0; n < 6; n++) {
            const int oc = n * 8 + 2 * u;
            float q0 = __shfl_xor_sync(0xffffffffu, acc[t][n][0], 4);
            float q1 = __shfl_xor_sync(0xffffffffu, acc[t][n][1], 4);
            float q2 = __shfl_xor_sync(0xffffffffu, acc[t][n][2], 4);
            float q3 = __shfl_xor_sync(0xffffffffu, acc[t][n][3], 4);
            if (!(g & 1)) {
                unsigned* base =
                    g_yh + ((size_t)(b * CMID + oc) * HH + h) * 128 + hc;
                base[0]                       = pack_h2(acc[t][n][0], q0);
                base[(size_t)HH * WW / 2]     = pack_h2(acc[t][n][1], q1);
                base[4]                       = pack_h2(acc[t][n][2], q2);
                base[(size_t)HH * WW / 2 + 4] = pack_h2(acc[t][n][3], q3);
            }
        }
    }
}

// ---------------------------------------------------------------------------
// Kernel B (R7 exact, 55us): fused pixel_unshuffle + mask interleave +
// grouped 3x3 conv. CTA: 16 rows x 128 cols, thread 2x4.
// ---------------------------------------------------------------------------
__global__ __launch_bounds__(256) void conv2_kernel(
    const float* __restrict__ mask, const float* __restrict__ wp,
    float* __restrict__ out)
{
    __shared__ __align__(16) float sy[2][18][132];
    __shared__ __align__(16) float smm[2][18][132];
    __shared__ float swp[36];

    const int tid = threadIdx.x;
    const int hb  = blockIdx.x * 16;
    const int gp  = blockIdx.y;     // (c, dy)
    const int b   = blockIdx.z;
    const int c   = gp >> 1;
    const int dy  = gp & 1;
    const int g0  = 4 * c + 2 * dy;

    if (tid < 36) swp[tid] = wp[g0 * 18 + tid];

    #pragma unroll
    for (int it = 0; it < 5; it++) {
        int idx = it * 256 + tid;
        if (idx < 1152) {
            int r  = idx >> 6;
            int q2 = (idx & 63) * 2;
            int gy = 2 * (hb - 1 + r) + dy;
            uint2 yv = make_uint2(0u, 0u);
            float4 mv = make_float4(0.f, 0.f, 0.f, 0.f);
            if ((unsigned)gy < (unsigned)HH) {
                yv = *(const uint2*)&g_yh[((size_t)(b * CMID + c) * HH + gy) * 128 + q2];
                mv = *(const float4*)&mask[((size_t)(b * HH) + gy) * WW + 2 * q2];
            }
            float2 f0 = h2f2(yv.x), f1 = h2f2(yv.y);
            sy[0][r][1 + q2] = f0.x;  sy[1][r][1 + q2] = f0.y;
            sy[0][r][2 + q2] = f1.x;  sy[1][r][2 + q2] = f1.y;
            smm[0][r][1 + q2] = mv.x; smm[1][r][1 + q2] = mv.y;
            smm[0][r][2 + q2] = mv.z; smm[1][r][2 + q2] = mv.w;
        }
    }
    if (tid < 18) {
        sy[0][tid][0] = 0.f;   sy[1][tid][0] = 0.f;
        sy[0][tid][129] = 0.f; sy[1][tid][129] = 0.f;
        smm[0][tid][0] = 0.f;   smm[1][tid][0] = 0.f;
        smm[0][tid][129] = 0.f; smm[1][tid][129] = 0.f;
    }
    __syncthreads();

    const int rr  = tid >> 5;
    const int w0c = (tid & 31) * 4;

    float a[2][2][4];
    #pragma unroll
    for (int o = 0; o < 2; o++)
        #pragma unroll
        for (int gx = 0; gx < 2; gx++)
            #pragma unroll
            for (int p = 0; p < 4; p++)
                a[o][gx][p] = 0.f;

    #pragma unroll
    for (int r = 0; r < 4; r++) {
        const int sr = 2 * rr + r;
        float4 ya0 = *(const float4*)&sy[0][sr][w0c];
        float2 yb0 = *(const float2*)&sy[0][sr][w0c + 4];
        float4 ya1 = *(const float4*)&sy[1][sr][w0c];
        float2 yb1 = *(const float2*)&sy[1][sr][w0c + 4];
        float4 ma0 = *(const float4*)&smm[0][sr][w0c];
        float2 mb0 = *(const float2*)&smm[0][sr][w0c + 4];
        float4 ma1 = *(const float4*)&smm[1][sr][w0c];
        float2 mb1 = *(const float2*)&smm[1][sr][w0c + 4];
        float yv0[6] = {ya0.x, ya0.y, ya0.z, ya0.w, yb0.x, yb0.y};
        float yv1[6] = {ya1.x, ya1.y, ya1.z, ya1.w, yb1.x, yb1.y};
        float mv0[6] = {ma0.x, ma0.y, ma0.z, ma0.w, mb0.x, mb0.y};
        float mv1[6] = {ma1.x, ma1.y, ma1.z, ma1.w, mb1.x, mb1.y};

        #pragma unroll
        for (int orow = 0; orow < 2; orow++) {
            const int kh = r - orow;
            if (kh < 0 || kh > 2) continue;
            #pragma unroll
            for (int kw = 0; kw < 3; kw++) {
                float wy0 = swp[kh * 3 + kw];
                float wm0 = swp[9 + kh * 3 + kw];
                float wy1 = swp[18 + kh * 3 + kw];
                float wm1 = swp[27 + kh * 3 + kw];
                #pragma unroll
                for (int p = 0; p < 4; p++) {
                    a[orow][0][p] = fmaf(wy0, yv0[kw + p], a[orow][0][p]);
                    a[orow][0][p] = fmaf(wm0, mv0[kw + p], a[orow][0][p]);
                    a[orow][1][p] = fmaf(wy1, yv1[kw + p], a[orow][1][p]);
                    a[orow][1][p] = fmaf(wm1, mv1[kw + p], a[orow][1][p]);
                }
            }
        }
    }

    #pragma unroll
    for (int orow = 0; orow < 2; orow++) {
        const int h = hb + 2 * rr + orow;
        *(float4*)&out[((size_t)(b * CO + g0) * H2 + h) * W2 + w0c] =
            make_float4(a[orow][0][0], a[orow][0][1], a[orow][0][2], a[orow][0][3]);
        *(float4*)&out[((size_t)(b * CO + g0 + 1) * H2 + h) * W2 + w0c] =
            make_float4(a[orow][1][0], a[orow][1][1], a[orow][1][2], a[orow][1][3]);
    }
}

// ---------------------------------------------------------------------------
extern "C" void kernel_launch(void* const* d_in, const int* in_sizes, int n_in,
                              void* d_out, int out_size)
{
    const float* x      = (const float*)d_in[0];
    const float* mask   = (const float*)d_in[1];
    const float* w_body = (const float*)d_in[2];
    const float* w_proj = (const float*)d_in[3];
    float* out = (float*)d_out;

    cudaFuncSetAttribute(conv1_mma_kernel,
                         cudaFuncAttributeMaxDynamicSharedMemorySize, SMEM_SZ);

    prep_kernel<<<(WN + PX_N + 255) / 256, 256>>>(x, w_body);

    dim3 g1(WW / 128, HH / 4, B_);      // (2, 64, 8) = 1024 CTAs
    conv1_mma_kernel<<<g1, 256, SMEM_SZ>>>();

    dim3 g2(H2 / 16, 96, B_);           // (8, 96, 8) = 6144 CTAs
    conv2_kernel<<<g2, 256>>>(mask, w_proj, out);
}